// round 5
// baseline (speedup 1.0000x reference)
#include <cuda_runtime.h>
#include <math.h>
#include <stdint.h>

// Problem constants
#define LAYERS 8
#define BATCH  256
#define TIME   8
#define EDIM   1024
#define HDIM   1024
#define KDIM   2048   // EDIM + HDIM

// Tiling
#define BM  64        // batch rows per block
#define BJG 32        // hidden cols per gate per block (block does 4 gates -> 128 cols)
#define BK  32        // k-slice per stage
#define NCHUNK (KDIM / BK)   // 64

// Scratch: ping-pong per-layer outputs (T,B,H) + running cell state (B,H)
__device__ float g_buf0[TIME * BATCH * HDIM];
__device__ float g_buf1[TIME * BATCH * HDIM];
__device__ float g_crun[BATCH * HDIM];

__device__ __forceinline__ uint32_t f2tf32(float f) {
    uint32_t r;
    asm("cvt.rna.tf32.f32 %0, %1;" : "=r"(r) : "f"(f));
    return r;
}

__device__ __forceinline__ void mma_tf32(float c[4],
                                         uint32_t a0, uint32_t a1, uint32_t a2, uint32_t a3,
                                         uint32_t b0, uint32_t b1) {
    asm volatile(
        "mma.sync.aligned.m16n8k8.row.col.f32.tf32.tf32.f32 "
        "{%0,%1,%2,%3}, {%4,%5,%6,%7}, {%8,%9}, {%0,%1,%2,%3};"
        : "+f"(c[0]), "+f"(c[1]), "+f"(c[2]), "+f"(c[3])
        : "r"(a0), "r"(a1), "r"(a2), "r"(a3), "r"(b0), "r"(b1));
}

// Smem per stage: A tile 64x32 in [k/4][m][k%4] layout (2048 floats)
//                 B tiles 4 gates x 32x32 in [k/4][n][k%4] layout (4096 floats)
// Two stages = 12288 floats = 48KB. Epilogue gate-exchange buffer (64x130) aliases it.
#define STAGE_FLOATS 6144
#define SB_OFF       2048
#define GS_STRIDE    130

__global__ __launch_bounds__(256, 1)
void lstm_step_mma(
    const float* __restrict__ inA, int strideA,      // (B x E) rows, row stride strideA
    const float* __restrict__ hprev,                 // (B x H)
    const float* __restrict__ Wu, const float* __restrict__ Wf,
    const float* __restrict__ Wo, const float* __restrict__ Wc,  // each (K2 x H) row-major
    const float* __restrict__ bu, const float* __restrict__ bf,
    const float* __restrict__ bo, const float* __restrict__ bc,
    const float* __restrict__ c_old_src,
    float* __restrict__ c_run,
    float* __restrict__ h_out,
    float* __restrict__ outH,        // base + t*H (row stride T*H) or null
    float* __restrict__ outC,
    float* __restrict__ outHt,
    float* __restrict__ outCt)
{
    __shared__ float smem[2 * STAGE_FLOATS];

    const int tid  = threadIdx.x;
    const int lane = tid & 31;
    const int warp = tid >> 5;
    const int wy   = warp >> 2;        // 0..1 : row half
    const int wx   = warp & 3;         // 0..3 : gate
    const int g4   = lane >> 2;        // groupID
    const int t4   = lane & 3;         // threadID in group
    const int j0   = blockIdx.x * BJG;
    const int b0   = blockIdx.y * BM;

    // Global-load thread mapping
    const int tA_m = tid >> 2;          // 0..63
    const int tA_k = (tid & 3) * 8;     // 0,8,16,24
    const int tB_k = tid >> 3;          // 0..31
    const int tB_j = (tid & 7) * 4;     // 0..28

    float acc[2][4][4];
    #pragma unroll
    for (int mi = 0; mi < 2; mi++)
        #pragma unroll
        for (int ni = 0; ni < 4; ni++)
            #pragma unroll
            for (int r = 0; r < 4; r++)
                acc[mi][ni][r] = 0.0f;

    float4 pA0, pA1, pW0, pW1, pW2, pW3;

    auto load_global = [&](int c) {
        const int k0 = c * BK;
        const float* aSrc;
        if (k0 < EDIM)
            aSrc = inA + (size_t)(b0 + tA_m) * strideA + (k0 + tA_k);
        else
            aSrc = hprev + (size_t)(b0 + tA_m) * HDIM + (k0 - EDIM + tA_k);
        pA0 = *(const float4*)aSrc;
        pA1 = *(const float4*)(aSrc + 4);
        const size_t wOff = (size_t)(k0 + tB_k) * HDIM + (j0 + tB_j);
        pW0 = *(const float4*)(Wu + wOff);
        pW1 = *(const float4*)(Wf + wOff);
        pW2 = *(const float4*)(Wo + wOff);
        pW3 = *(const float4*)(Wc + wOff);
    };

    auto store_smem = [&](int s) {
        float* sA = smem + s * STAGE_FLOATS;
        float* sB = sA + SB_OFF;
        // A: two float4 stores into [k/4][m][k%4]
        const int aIdx = (tA_k >> 2) * 256 + tA_m * 4;
        uint4 u0 = make_uint4(f2tf32(pA0.x), f2tf32(pA0.y), f2tf32(pA0.z), f2tf32(pA0.w));
        uint4 u1 = make_uint4(f2tf32(pA1.x), f2tf32(pA1.y), f2tf32(pA1.z), f2tf32(pA1.w));
        *(uint4*)(sA + aIdx)       = u0;
        *(uint4*)(sA + aIdx + 256) = u1;
        // B: scatter (stride 4 between consecutive n)
        const int bBase = (tB_k >> 2) * 128 + tB_j * 4 + (tB_k & 3);
        #define STG(gi, v)                                                     \
            sB[(gi)*1024 + bBase +  0] = __uint_as_float(f2tf32((v).x));       \
            sB[(gi)*1024 + bBase +  4] = __uint_as_float(f2tf32((v).y));       \
            sB[(gi)*1024 + bBase +  8] = __uint_as_float(f2tf32((v).z));       \
            sB[(gi)*1024 + bBase + 12] = __uint_as_float(f2tf32((v).w));
        STG(0, pW0) STG(1, pW1) STG(2, pW2) STG(3, pW3)
        #undef STG
    };

    const int aOff = (32 * wy + g4) * 4 + t4;
    const int bOff = wx * 1024 + g4 * 4 + t4;

    auto compute = [&](int s) {
        const float* sA = smem + s * STAGE_FLOATS;
        const float* sB = sA + SB_OFF;
        #pragma unroll
        for (int q = 0; q < 4; q++) {
            uint32_t a[2][4];
            #pragma unroll
            for (int mi = 0; mi < 2; mi++) {
                const int base = aOff + 512 * q + 64 * mi;
                a[mi][0] = __float_as_uint(sA[base]);
                a[mi][1] = __float_as_uint(sA[base + 32]);
                a[mi][2] = __float_as_uint(sA[base + 256]);
                a[mi][3] = __float_as_uint(sA[base + 288]);
            }
            #pragma unroll
            for (int ni = 0; ni < 4; ni++) {
                const int bb = bOff + 256 * q + 32 * ni;
                const uint32_t bb0 = __float_as_uint(sB[bb]);
                const uint32_t bb1 = __float_as_uint(sB[bb + 128]);
                mma_tf32(acc[0][ni], a[0][0], a[0][1], a[0][2], a[0][3], bb0, bb1);
                mma_tf32(acc[1][ni], a[1][0], a[1][1], a[1][2], a[1][3], bb0, bb1);
            }
        }
    };

    // Pipelined main loop
    load_global(0);
    store_smem(0);
    __syncthreads();

    #pragma unroll 1
    for (int c = 0; c < NCHUNK; c++) {
        const int s = c & 1;
        if (c + 1 < NCHUNK) load_global(c + 1);
        compute(s);
        if (c + 1 < NCHUNK) {
            __syncthreads();
            store_smem(s ^ 1);
            __syncthreads();
        }
    }

    // Epilogue: exchange gates through smem, fused cell update
    __syncthreads();
    float* gs = smem;   // 64 x 130
    #pragma unroll
    for (int mi = 0; mi < 2; mi++) {
        #pragma unroll
        for (int ni = 0; ni < 4; ni++) {
            const int row = 32 * wy + 16 * mi + g4;
            const int col = wx * 32 + ni * 8 + t4 * 2;
            *(float2*)(gs + row * GS_STRIDE + col) =
                make_float2(acc[mi][ni][0], acc[mi][ni][1]);
            *(float2*)(gs + (row + 8) * GS_STRIDE + col) =
                make_float2(acc[mi][ni][2], acc[mi][ni][3]);
        }
    }
    __syncthreads();

    const int jj = tid & 31;
    const int r0 = tid >> 5;
    const int j  = j0 + jj;
    const float b_u = bu[j], b_f = bf[j], b_o = bo[j], b_c = bc[j];

    #pragma unroll
    for (int i = 0; i < 8; i++) {
        const int row = r0 + 8 * i;
        const int b   = b0 + row;
        const size_t idx = (size_t)b * HDIM + j;
        const float u  = 1.0f / (1.0f + expf(-(gs[row * GS_STRIDE +       jj] + b_u)));
        const float f  = 1.0f / (1.0f + expf(-(gs[row * GS_STRIDE + 32 + jj] + b_f)));
        const float o  = 1.0f / (1.0f + expf(-(gs[row * GS_STRIDE + 64 + jj] + b_o)));
        const float ct = tanhf(gs[row * GS_STRIDE + 96 + jj] + b_c);
        const float c_old = c_old_src[idx];
        const float c_new = f * c_old + u * ct;
        const float h_new = o * tanhf(c_new);
        c_run[idx] = c_new;
        h_out[idx] = h_new;
        if (outH) {
            const size_t oidx = (size_t)b * (TIME * HDIM) + j;
            outH[oidx] = h_new;
            outC[oidx] = c_new;
            if (outHt) {
                outHt[idx] = h_new;
                outCt[idx] = c_new;
            }
        }
    }
}

extern "C" void kernel_launch(void* const* d_in, const int* in_sizes, int n_in,
                              void* d_out, int out_size) {
    const float* x  = (const float*)d_in[0];   // (B, T, E)
    const float* h0 = (const float*)d_in[1];   // (L, B, H)
    const float* c0 = (const float*)d_in[2];   // (L, B, H)
    const float* Wu = (const float*)d_in[3];   // (L, K2, H)
    const float* bu = (const float*)d_in[4];   // (L, H)
    const float* Wf = (const float*)d_in[5];
    const float* bf = (const float*)d_in[6];
    const float* Wo = (const float*)d_in[7];
    const float* bo = (const float*)d_in[8];
    const float* Wc = (const float*)d_in[9];
    const float* bc = (const float*)d_in[10];

    float* out = (float*)d_out;
    float* outHidden = out;                                        // (B, T, H)
    float* outMem    = out + (size_t)BATCH * TIME * HDIM;          // (B, T, H)
    float* outHt     = out + (size_t)2 * BATCH * TIME * HDIM;      // (B, 1, H)
    float* outCt     = outHt + (size_t)BATCH * HDIM;               // (B, 1, H)

    float *buf0, *buf1, *crun;
    cudaGetSymbolAddress((void**)&buf0, g_buf0);
    cudaGetSymbolAddress((void**)&buf1, g_buf1);
    cudaGetSymbolAddress((void**)&crun, g_crun);

    const dim3 grid(HDIM / BJG, BATCH / BM);  // (32, 4) = 128 blocks
    const dim3 block(256);

    // Layer-outer, time-inner: keeps one layer's 32 MB of weights L2-resident
    // across all 8 timesteps.
    for (int l = 0; l < LAYERS; l++) {
        const size_t wOff = (size_t)l * KDIM * HDIM;
        const size_t bOff = (size_t)l * HDIM;
        const float* Wu_l = Wu + wOff;
        const float* Wf_l = Wf + wOff;
        const float* Wo_l = Wo + wOff;
        const float* Wc_l = Wc + wOff;
        const float* bu_l = bu + bOff;
        const float* bf_l = bf + bOff;
        const float* bo_l = bo + bOff;
        const float* bc_l = bc + bOff;

        float* cur        = (l & 1) ? buf1 : buf0;
        const float* prev = (l & 1) ? buf0 : buf1;
        const bool last = (l == LAYERS - 1);

        for (int t = 0; t < TIME; t++) {
            const float* inA;
            int strideA;
            if (l == 0) {
                inA = x + (size_t)t * EDIM;      // x[b][t][:] with row stride T*E
                strideA = TIME * EDIM;
            } else {
                inA = prev + (size_t)t * BATCH * HDIM;
                strideA = HDIM;
            }
            const float* hprev = (t == 0) ? (h0 + (size_t)l * BATCH * HDIM)
                                          : (cur + (size_t)(t - 1) * BATCH * HDIM);
            const float* coldsrc = (t == 0) ? (c0 + (size_t)l * BATCH * HDIM) : crun;
            float* hout = cur + (size_t)t * BATCH * HDIM;

            float* oH  = last ? (outHidden + (size_t)t * HDIM) : nullptr;
            float* oC  = last ? (outMem + (size_t)t * HDIM) : nullptr;
            float* oHt = (last && t == TIME - 1) ? outHt : nullptr;
            float* oCt = (last && t == TIME - 1) ? outCt : nullptr;

            lstm_step_mma<<<grid, block>>>(
                inA, strideA, hprev,
                Wu_l, Wf_l, Wo_l, Wc_l,
                bu_l, bf_l, bo_l, bc_l,
                coldsrc, crun, hout,
                oH, oC, oHt, oCt);
        }
    }
}

// round 6
// speedup vs baseline: 1.3770x; 1.3770x over previous
#include <cuda_runtime.h>
#include <math.h>
#include <stdint.h>

// Problem constants
#define LAYERS 8
#define BATCH  256
#define TIME   8
#define EDIM   1024
#define HDIM   1024

// Tiling
#define BM   64      // rows per block
#define BJG  32      // cols per gate per block (block covers 4 gates = 128 cols)
#define BK   16      // k per stage
#define STAGES 3

#define A_STRIDE 20              // 16 + 4 pad  (bank step 4 per row)
#define B_STRIDE 40              // 32 + 8 pad  (bank step 8 per k-row)
#define SB_OFF   (64 * A_STRIDE)           // 1280 floats
#define STAGE_F  (SB_OFF + 64 * B_STRIDE)  // 1280 + 2560 = 3840 floats
#define SMEM_F   (STAGES * STAGE_F)        // 11520 floats = 46080 B (< 48KB static)
#define GS_STRIDE 130

// Scratch buffers
__device__ float g_buf0[BATCH * TIME * HDIM];          // layer outputs, (B,T,H)
__device__ float g_buf1[BATCH * TIME * HDIM];
__device__ float g_crun[BATCH * HDIM];                 // running cell state
__device__ float g_pre[(size_t)BATCH * TIME * 4 * HDIM]; // x-part gate preacts

__device__ __forceinline__ uint32_t f2tf32(float f) {
    uint32_t r;
    asm("cvt.rna.tf32.f32 %0, %1;" : "=r"(r) : "f"(f));
    return r;
}

__device__ __forceinline__ void mma_tf32(float c[4],
                                         uint32_t a0, uint32_t a1, uint32_t a2, uint32_t a3,
                                         uint32_t b0, uint32_t b1) {
    asm volatile(
        "mma.sync.aligned.m16n8k8.row.col.f32.tf32.tf32.f32 "
        "{%0,%1,%2,%3}, {%4,%5,%6,%7}, {%8,%9}, {%0,%1,%2,%3};"
        : "+f"(c[0]), "+f"(c[1]), "+f"(c[2]), "+f"(c[3])
        : "r"(a0), "r"(a1), "r"(a2), "r"(a3), "r"(b0), "r"(b1));
}

__device__ __forceinline__ void cp16(uint32_t dst, const float* src) {
    asm volatile("cp.async.cg.shared.global [%0], [%1], 16;" :: "r"(dst), "l"(src));
}
__device__ __forceinline__ void cp_commit() {
    asm volatile("cp.async.commit_group;");
}
template <int N> __device__ __forceinline__ void cp_wait() {
    asm volatile("cp.async.wait_group %0;" :: "n"(N));
}

// Shared GEMM mainloop: acc[2][4][4] += A[r0:r0+64, :KT*16] @ [Wu|Wf|Wo|Wc][:, j0:j0+32]
// A rows at Aptr + row*strideA (fp32); W row-major (k, HDIM).
__device__ __forceinline__ void gemm_main(
    float* smem,
    const float* __restrict__ Aptr, int strideA, int r0,
    const float* __restrict__ Wu, const float* __restrict__ Wf,
    const float* __restrict__ Wo, const float* __restrict__ Wc,
    int j0, int KT, float acc[2][4][4])
{
    const int tid  = threadIdx.x;
    const int lane = tid & 31;
    const int warp = tid >> 5;
    const int wy   = warp >> 2;   // row half
    const int wx   = warp & 3;    // gate
    const int g4   = lane >> 2;
    const int t4   = lane & 3;

    // cp.async mapping
    const int aRow = tid >> 2;          // 0..63
    const int aSeg = tid & 3;           // 0..3  (16 floats/row = 4 x 16B)
    const int bGr  = tid >> 2;          // 0..63 = gate*16 + kk
    const int bG   = bGr >> 4;
    const int bKK  = bGr & 15;
    const int bSeg0 = (tid & 3) * 2;    // 2 consecutive 16B segs (32 floats/row = 8 segs)
    const float* Wsel = (bG == 0) ? Wu : (bG == 1) ? Wf : (bG == 2) ? Wo : Wc;

    auto issue = [&](int c) {
        const int slot = c % STAGES;
        float* sA = smem + slot * STAGE_F;
        float* sB = sA + SB_OFF;
        const int k0 = c * BK;
        cp16((uint32_t)__cvta_generic_to_shared(sA + aRow * A_STRIDE + aSeg * 4),
             Aptr + (size_t)(r0 + aRow) * strideA + k0 + aSeg * 4);
        const float* wsrc = Wsel + (size_t)(k0 + bKK) * HDIM + j0 + bSeg0 * 4;
        float* wdst = sB + bGr * B_STRIDE + bSeg0 * 4;
        cp16((uint32_t)__cvta_generic_to_shared(wdst),     wsrc);
        cp16((uint32_t)__cvta_generic_to_shared(wdst + 4), wsrc + 4);
        cp_commit();
    };

    auto compute = [&](int slot) {
        const float* sA = smem + slot * STAGE_F;
        const float* sB = sA + SB_OFF;
        #pragma unroll
        for (int q = 0; q < 2; q++) {
            const int kk = 8 * q + t4;
            uint32_t a[2][4];
            #pragma unroll
            for (int mi = 0; mi < 2; mi++) {
                const int row = 32 * wy + 16 * mi + g4;
                a[mi][0] = f2tf32(sA[row * A_STRIDE + kk]);
                a[mi][1] = f2tf32(sA[(row + 8) * A_STRIDE + kk]);
                a[mi][2] = f2tf32(sA[row * A_STRIDE + kk + 4]);
                a[mi][3] = f2tf32(sA[(row + 8) * A_STRIDE + kk + 4]);
            }
            const int krow = wx * 16 + 8 * q + t4;
            #pragma unroll
            for (int ni = 0; ni < 4; ni++) {
                const int col = 8 * ni + g4;
                const uint32_t b0 = f2tf32(sB[krow * B_STRIDE + col]);
                const uint32_t b1 = f2tf32(sB[(krow + 4) * B_STRIDE + col]);
                mma_tf32(acc[0][ni], a[0][0], a[0][1], a[0][2], a[0][3], b0, b1);
                mma_tf32(acc[1][ni], a[1][0], a[1][1], a[1][2], a[1][3], b0, b1);
            }
        }
    };

    // Prologue: stages 0..STAGES-2
    #pragma unroll
    for (int s = 0; s < STAGES - 1; s++) issue(s);

    #pragma unroll 1
    for (int c = 0; c < KT; c++) {
        if (c + STAGES - 1 < KT) issue(c + STAGES - 1); else cp_commit();
        cp_wait<STAGES - 1>();     // oldest (stage c) complete
        __syncthreads();
        compute(c % STAGES);
        __syncthreads();
    }
}

// ---------------------------------------------------------------------------
// Pre-kernel: x-part GEMM for a whole layer (all timesteps at once).
// Rows r = b*T + t; G_pre[r][gate][j] = A[r,:] @ Wg[0:1024, j]
// ---------------------------------------------------------------------------
__global__ __launch_bounds__(256, 1)
void lstm_pre(const float* __restrict__ A, int strideA,
              const float* __restrict__ Wu, const float* __restrict__ Wf,
              const float* __restrict__ Wo, const float* __restrict__ Wc,
              float* __restrict__ Gpre)
{
    __shared__ float smem[SMEM_F];
    const int j0 = blockIdx.x * BJG;
    const int r0 = blockIdx.y * BM;

    float acc[2][4][4];
    #pragma unroll
    for (int mi = 0; mi < 2; mi++)
        #pragma unroll
        for (int ni = 0; ni < 4; ni++)
            #pragma unroll
            for (int r = 0; r < 4; r++) acc[mi][ni][r] = 0.0f;

    gemm_main(smem, A, strideA, r0, Wu, Wf, Wo, Wc, j0, EDIM / BK, acc);

    const int lane = threadIdx.x & 31;
    const int warp = threadIdx.x >> 5;
    const int wy = warp >> 2, wx = warp & 3;
    const int g4 = lane >> 2, t4 = lane & 3;

    #pragma unroll
    for (int mi = 0; mi < 2; mi++) {
        #pragma unroll
        for (int ni = 0; ni < 4; ni++) {
            const int row = r0 + 32 * wy + 16 * mi + g4;
            const int col = j0 + 8 * ni + 2 * t4;
            *(float2*)(Gpre + ((size_t)row * 4 + wx) * HDIM + col) =
                make_float2(acc[mi][ni][0], acc[mi][ni][1]);
            *(float2*)(Gpre + ((size_t)(row + 8) * 4 + wx) * HDIM + col) =
                make_float2(acc[mi][ni][2], acc[mi][ni][3]);
        }
    }
}

// ---------------------------------------------------------------------------
// Step kernel: h-recurrent GEMM (K=1024) + fused LSTM cell update.
// ---------------------------------------------------------------------------
__global__ __launch_bounds__(256, 1)
void lstm_step(const float* __restrict__ hbase, int hstride,   // A rows: batch b
               const float* __restrict__ Wu, const float* __restrict__ Wf,
               const float* __restrict__ Wo, const float* __restrict__ Wc, // +EDIM*H offset
               const float* __restrict__ bu, const float* __restrict__ bf,
               const float* __restrict__ bo, const float* __restrict__ bc,
               const float* __restrict__ Gpre, int t,
               const float* __restrict__ c_old_src,   // (B,H)
               float* __restrict__ c_run,             // (B,H)
               float* __restrict__ hrow,              // curbase + t*H, row stride T*H
               float* __restrict__ crow,              // outMem + t*H or null
               float* __restrict__ outHt, float* __restrict__ outCt)
{
    __shared__ float smem[SMEM_F];
    const int j0 = blockIdx.x * BJG;
    const int b0 = blockIdx.y * BM;

    float acc[2][4][4];
    #pragma unroll
    for (int mi = 0; mi < 2; mi++)
        #pragma unroll
        for (int ni = 0; ni < 4; ni++)
            #pragma unroll
            for (int r = 0; r < 4; r++) acc[mi][ni][r] = 0.0f;

    gemm_main(smem, hbase, hstride, b0, Wu, Wf, Wo, Wc, j0, HDIM / BK, acc);

    // Gate exchange through smem (aliases pipeline buffers; mainloop ended with sync)
    cp_wait<0>();
    __syncthreads();
    float* gs = smem;   // 64 x 130
    {
        const int lane = threadIdx.x & 31;
        const int warp = threadIdx.x >> 5;
        const int wy = warp >> 2, wx = warp & 3;
        const int g4 = lane >> 2, t4 = lane & 3;
        #pragma unroll
        for (int mi = 0; mi < 2; mi++) {
            #pragma unroll
            for (int ni = 0; ni < 4; ni++) {
                const int row = 32 * wy + 16 * mi + g4;
                const int col = wx * 32 + 8 * ni + 2 * t4;
                *(float2*)(gs + row * GS_STRIDE + col) =
                    make_float2(acc[mi][ni][0], acc[mi][ni][1]);
                *(float2*)(gs + (row + 8) * GS_STRIDE + col) =
                    make_float2(acc[mi][ni][2], acc[mi][ni][3]);
            }
        }
    }
    __syncthreads();

    const int jj = threadIdx.x & 31;
    const int r0 = threadIdx.x >> 5;
    const int j  = j0 + jj;
    const float b_u = bu[j], b_f = bf[j], b_o = bo[j], b_c = bc[j];

    #pragma unroll
    for (int i = 0; i < 8; i++) {
        const int row = r0 + 8 * i;
        const int b   = b0 + row;
        const size_t gbase = ((size_t)(b * TIME + t) * 4) * HDIM + j;
        const float su = gs[row * GS_STRIDE +      jj] + Gpre[gbase]            + b_u;
        const float sf = gs[row * GS_STRIDE + 32 + jj] + Gpre[gbase +     HDIM] + b_f;
        const float so = gs[row * GS_STRIDE + 64 + jj] + Gpre[gbase + 2 * HDIM] + b_o;
        const float sc = gs[row * GS_STRIDE + 96 + jj] + Gpre[gbase + 3 * HDIM] + b_c;
        const float u  = 1.0f / (1.0f + expf(-su));
        const float f  = 1.0f / (1.0f + expf(-sf));
        const float o  = 1.0f / (1.0f + expf(-so));
        const float ct = tanhf(sc);
        const size_t idx = (size_t)b * HDIM + j;
        const float c_new = f * c_old_src[idx] + u * ct;
        const float h_new = o * tanhf(c_new);
        c_run[idx] = c_new;
        hrow[(size_t)b * (TIME * HDIM) + j] = h_new;
        if (crow) crow[(size_t)b * (TIME * HDIM) + j] = c_new;
        if (outHt) { outHt[idx] = h_new; outCt[idx] = c_new; }
    }
}

extern "C" void kernel_launch(void* const* d_in, const int* in_sizes, int n_in,
                              void* d_out, int out_size) {
    const float* x  = (const float*)d_in[0];   // (B, T, E)
    const float* h0 = (const float*)d_in[1];   // (L, B, H)
    const float* c0 = (const float*)d_in[2];   // (L, B, H)
    const float* Wu = (const float*)d_in[3];   // (L, 2048, H)
    const float* bu = (const float*)d_in[4];   // (L, H)
    const float* Wf = (const float*)d_in[5];
    const float* bf = (const float*)d_in[6];
    const float* Wo = (const float*)d_in[7];
    const float* bo = (const float*)d_in[8];
    const float* Wc = (const float*)d_in[9];
    const float* bc = (const float*)d_in[10];

    float* out = (float*)d_out;
    float* outHidden = out;                                   // (B, T, H)
    float* outMem    = out + (size_t)BATCH * TIME * HDIM;     // (B, T, H)
    float* outHt     = out + (size_t)2 * BATCH * TIME * HDIM; // (B, 1, H)
    float* outCt     = outHt + (size_t)BATCH * HDIM;          // (B, 1, H)

    float *buf0, *buf1, *crun, *gpre;
    cudaGetSymbolAddress((void**)&buf0, g_buf0);
    cudaGetSymbolAddress((void**)&buf1, g_buf1);
    cudaGetSymbolAddress((void**)&crun, g_crun);
    cudaGetSymbolAddress((void**)&gpre, g_pre);

    const dim3 blk(256);
    const dim3 gridPre(HDIM / BJG, (BATCH * TIME) / BM);  // (32, 32) = 1024
    const dim3 gridStep(HDIM / BJG, BATCH / BM);          // (32, 4)  = 128

    for (int l = 0; l < LAYERS; l++) {
        const size_t wOff = (size_t)l * 2048 * HDIM;
        const size_t bOff = (size_t)l * HDIM;
        const float* Wu_l = Wu + wOff;
        const float* Wf_l = Wf + wOff;
        const float* Wo_l = Wo + wOff;
        const float* Wc_l = Wc + wOff;

        const float* Aprev;
        int strideA;
        if (l == 0) { Aprev = x; strideA = EDIM; }                 // rows r=b*T+t
        else { Aprev = ((l - 1) & 1) ? buf1 : buf0; strideA = HDIM; }
        float* cur = (l == LAYERS - 1) ? outHidden : ((l & 1) ? buf1 : buf0);
        const bool last = (l == LAYERS - 1);

        // Parallel x-part GEMM for all timesteps of this layer
        lstm_pre<<<gridPre, blk>>>(Aprev, strideA, Wu_l, Wf_l, Wo_l, Wc_l, gpre);

        // Sequential h-recurrent part
        const float* Wu_h = Wu_l + (size_t)EDIM * HDIM;
        const float* Wf_h = Wf_l + (size_t)EDIM * HDIM;
        const float* Wo_h = Wo_l + (size_t)EDIM * HDIM;
        const float* Wc_h = Wc_l + (size_t)EDIM * HDIM;

        for (int t = 0; t < TIME; t++) {
            const float* hbase;
            int hstride;
            if (t == 0) { hbase = h0 + (size_t)l * BATCH * HDIM; hstride = HDIM; }
            else        { hbase = cur + (size_t)(t - 1) * HDIM;  hstride = TIME * HDIM; }
            const float* coldsrc = (t == 0) ? (c0 + (size_t)l * BATCH * HDIM) : crun;
            float* hrow = cur + (size_t)t * HDIM;
            float* crow = last ? (outMem + (size_t)t * HDIM) : nullptr;
            float* oHt  = (last && t == TIME - 1) ? outHt : nullptr;
            float* oCt  = (last && t == TIME - 1) ? outCt : nullptr;

            lstm_step<<<gridStep, blk>>>(hbase, hstride,
                                         Wu_h, Wf_h, Wo_h, Wc_h,
                                         bu + bOff, bf + bOff, bo + bOff, bc + bOff,
                                         gpre, t, coldsrc, crun, hrow, crow, oHt, oCt);
        }
    }
}